// round 3
// baseline (speedup 1.0000x reference)
#include <cuda_runtime.h>

// AssociatorLoss: B=32, N=32
//   one[b,i,j,k,l] = sum_m a[b,i,m,l] * a[b,j,k,m]
//   two[b,i,j,k,l] = sum_m a[b,m,k,l] * a[b,i,j,m]
//   KL = sum two * log(two/one) / B
//
// CTA = (b,i); full a[b] cube (128 KB) staged in SMEM with XOR swizzle on
// float4 chunks within each 32-float row (conflict-free for both row-major
// and k-strided transposed reads).
//
// R1->R2 change (unmeasured in R2 due to broker failure; resubmitted):
// per-thread tile shrunk 4jx8l -> 4jx4l over 4 l-phases so the live
// register set (~90) fits the 128-reg/thread budget at 512 thr/CTA with
// NO spills (R0/R1 demanded ~150 regs -> local-memory spills in the hot
// loop, measured 2.2x over the FFMA-pipe floor).

__device__ float g_partial[1024];

// Accurate natural log: reduce to z in [sqrt(2)/2, sqrt(2)), atanh series.
// |abs err| ~1e-7; keeps the 33M-term KL sum far inside the 1e-3 tolerance.
__device__ __forceinline__ float acc_logf(float x) {
    int ix = __float_as_int(x);
    int t  = ix - 0x3f3504f3;
    int e  = t >> 23;
    float z = __int_as_float(ix - (t & 0xff800000));
    float f = z - 1.0f;
    float s = __fdividef(f, 2.0f + f);
    float s2 = s * s;
    float p = fmaf(s2, fmaf(s2, fmaf(s2, 0.28571429f, 0.4f), 0.66666667f), 2.0f);
    return fmaf((float)e, 0.69314718f, s * p);
}

__global__ __launch_bounds__(512, 1)
void assoc_kernel(const float* __restrict__ A) {
    extern __shared__ float4 sc[];        // 8192 float4 = 128 KB, swizzled cube

    const int i = blockIdx.x;             // 0..31
    const int b = blockIdx.y;             // 0..31
    const float4* ab4 = reinterpret_cast<const float4*>(A + b * 32768);
    const int tid = threadIdx.x;

    // ---- stage a[b] into SMEM, swizzled: chunk c of row r -> c ^ (r & 7) ----
    #pragma unroll
    for (int it = 0; it < 16; ++it) {
        int g = it * 512 + tid;                       // coalesced float4 index
        float4 v = ab4[g];
        int pos = (g & ~7) | ((g ^ (g >> 3)) & 7);    // row*8 + (c ^ (row&7))
        sc[pos] = v;
    }
    __syncthreads();

    const int k   = tid & 31;        // lane = k
    const int jg  = (tid >> 5) & 7;  // 8 j-groups of 4
    const int lh  = tid >> 8;        // l-half (0/1): chunks lh*4 .. lh*4+3
    const int jb  = jg * 4;
    const int ks  = k & 7;

    float kl = 0.0f;

    #pragma unroll
    for (int p = 0; p < 4; ++p) {
        const int c = lh * 4 + p;             // l chunk: l = c*4 + lw

        float acc1[4][4], acc2[4][4];
        #pragma unroll
        for (int jj = 0; jj < 4; ++jj)
            #pragma unroll
            for (int lw = 0; lw < 4; ++lw) { acc1[jj][lw] = 0.0f; acc2[jj][lw] = 0.0f; }

        #pragma unroll
        for (int mc = 0; mc < 8; ++mc) {      // m = mc*4 + mm
            float4 rm4[4], aj4[4];
            #pragma unroll
            for (int jj = 0; jj < 4; ++jj) {
                int j = jb + jj;
                // rm4[jj] = a[b, j, k, mc*4 .. mc*4+3]   (k-strided, swizzled)
                rm4[jj] = sc[(j * 32 + k) * 8 + (mc ^ ks)];
                // aj4[jj] = a[b, i, j, mc*4 .. mc*4+3]   (warp-broadcast)
                aj4[jj] = sc[(i * 32 + j) * 8 + (mc ^ (j & 7))];
            }

            #define MM_STEP(MM)                                                     \
            {                                                                        \
                const int m = mc * 4 + (MM);                                         \
                const int ms = m & 7;                                                \
                float4 s0 = sc[(i * 32 + m) * 8 + (c ^ ms)];  /* a[b,i,m,l] bc */    \
                float4 v0 = sc[(m * 32 + k) * 8 + (c ^ ks)];  /* a[b,m,k,l]   */     \
                _Pragma("unroll")                                                    \
                for (int jj = 0; jj < 4; ++jj) {                                     \
                    float aj = ((const float*)&aj4[jj])[(MM)];                       \
                    float rv = ((const float*)&rm4[jj])[(MM)];                       \
                    acc2[jj][0] = fmaf(aj, v0.x, acc2[jj][0]);                       \
                    acc2[jj][1] = fmaf(aj, v0.y, acc2[jj][1]);                       \
                    acc2[jj][2] = fmaf(aj, v0.z, acc2[jj][2]);                       \
                    acc2[jj][3] = fmaf(aj, v0.w, acc2[jj][3]);                       \
                    acc1[jj][0] = fmaf(rv, s0.x, acc1[jj][0]);                       \
                    acc1[jj][1] = fmaf(rv, s0.y, acc1[jj][1]);                       \
                    acc1[jj][2] = fmaf(rv, s0.z, acc1[jj][2]);                       \
                    acc1[jj][3] = fmaf(rv, s0.w, acc1[jj][3]);                       \
                }                                                                    \
            }
            MM_STEP(0) MM_STEP(1) MM_STEP(2) MM_STEP(3)
            #undef MM_STEP
        }

        // ---- KL for this 4x4 tile: two * log(two/one) ----
        #pragma unroll
        for (int jj = 0; jj < 4; ++jj)
            #pragma unroll
            for (int lw = 0; lw < 4; ++lw) {
                float two = acc2[jj][lw];
                float one = acc1[jj][lw];
                float q = __fdividef(two, one);
                kl = fmaf(two, acc_logf(q), kl);
            }
    }

    // ---- deterministic block reduction ----
    #pragma unroll
    for (int o = 16; o > 0; o >>= 1)
        kl += __shfl_xor_sync(0xffffffffu, kl, o);

    __syncthreads();                       // smem reuse safe: all reads done
    float* sred = reinterpret_cast<float*>(sc);
    if ((tid & 31) == 0) sred[tid >> 5] = kl;
    __syncthreads();
    if (tid < 16) {
        float v = sred[tid];
        #pragma unroll
        for (int o = 8; o > 0; o >>= 1)
            v += __shfl_xor_sync(0xffffu, v, o);
        if (tid == 0) g_partial[b * 32 + i] = v;
    }
}

__global__ void reduce_kernel(float* __restrict__ out) {
    int tid = threadIdx.x;                 // 32 threads, 1 warp
    double s = 0.0;
    #pragma unroll
    for (int it = 0; it < 32; ++it)
        s += (double)g_partial[it * 32 + tid];
    #pragma unroll
    for (int o = 16; o > 0; o >>= 1)
        s += __shfl_xor_sync(0xffffffffu, s, o);
    if (tid == 0) out[0] = (float)(s * (1.0 / 32.0));   // / B
}

extern "C" void kernel_launch(void* const* d_in, const int* in_sizes, int n_in,
                              void* d_out, int out_size) {
    const float* A = (const float*)d_in[0];
    float* out = (float*)d_out;

    cudaFuncSetAttribute(assoc_kernel,
                         cudaFuncAttributeMaxDynamicSharedMemorySize, 131072);

    dim3 grid(32, 32);   // (i, b)
    assoc_kernel<<<grid, 512, 131072>>>(A);
    reduce_kernel<<<1, 32>>>(out);
}